// round 3
// baseline (speedup 1.0000x reference)
#include <cuda_runtime.h>
#include <cuda_bf16.h>

#define N_NODES 50000
#define N_EDGES 800000
#define D 64
#define NSCAN   (N_NODES + 1)     // 50001
#define SCAN_BLK 1024
#define SCAN_NBLK ((NSCAN + SCAN_BLK - 1) / SCAN_BLK)   // 49

// ---- device-global scratch (no allocations allowed) ----
__device__ __align__(16) float g_exp_s[N_EDGES];
__device__ __align__(16) float g_denom[N_NODES];
__device__ __align__(16) float g_hsum[N_NODES * D];
__device__ __align__(16) int   g_count[NSCAN];
__device__ __align__(16) int   g_off[NSCAN];
__device__ __align__(16) int   g_cursor[N_NODES];
__device__ __align__(16) int2  g_perm[N_EDGES];     // (src, edge)
__device__            int   g_part[SCAN_NBLK];
__device__            int   g_base[64];

// ---------------------------------------------------------------------------
// Zero counts + denom (tiny: ~400KB). g_hsum no longer needs zeroing — the
// aggregate kernel fully writes it (including zero rows for edge-less nodes).
// ---------------------------------------------------------------------------
__global__ void kgcn_zero_kernel() {
    int i = blockIdx.x * blockDim.x + threadIdx.x;
    if (i < NSCAN) g_count[i] = 0;
    if (i < N_NODES) g_denom[i] = 0.f;
}

// ---------------------------------------------------------------------------
// Kernel 1: score = exp(dot(h_src[src], e)); atomic denom + degree histogram.
// Half-warp (16 lanes x float4) per edge = exactly one 256B row per group.
// ---------------------------------------------------------------------------
__global__ void kgcn_score_kernel(const float* __restrict__ h_src,
                                  const float* __restrict__ e,
                                  const int* __restrict__ src,
                                  const int* __restrict__ dst) {
    int tid  = blockIdx.x * blockDim.x + threadIdx.x;
    int edge = tid >> 4;
    int sub  = tid & 15;
    if (edge >= N_EDGES) return;   // never taken: E*16 == grid exactly

    int s = src[edge];
    float4 hv = reinterpret_cast<const float4*>(h_src)[(size_t)s * 16 + sub];
    float4 ev = reinterpret_cast<const float4*>(e)[(size_t)edge * 16 + sub];

    float dot = hv.x * ev.x + hv.y * ev.y + hv.z * ev.z + hv.w * ev.w;
    dot += __shfl_xor_sync(0xffffffffu, dot, 1);
    dot += __shfl_xor_sync(0xffffffffu, dot, 2);
    dot += __shfl_xor_sync(0xffffffffu, dot, 4);
    dot += __shfl_xor_sync(0xffffffffu, dot, 8);

    if (sub == 0) {
        int d = dst[edge];
        float ex = __expf(dot);
        g_exp_s[edge] = ex;
        atomicAdd(&g_denom[d], ex);
        atomicAdd(&g_count[d], 1);
    }
}

// ---------------------------------------------------------------------------
// Scan phase 1: per-block exclusive scan of g_count into g_off (no base),
// block totals into g_part.
// ---------------------------------------------------------------------------
__global__ void __launch_bounds__(SCAN_BLK) kgcn_scan1_kernel() {
    __shared__ int wsum[32];
    int tid = threadIdx.x;
    int i = blockIdx.x * SCAN_BLK + tid;
    int v = (i < NSCAN) ? g_count[i] : 0;

    int lane = tid & 31, wid = tid >> 5;
    int x = v;
    #pragma unroll
    for (int dd = 1; dd < 32; dd <<= 1) {
        int y = __shfl_up_sync(0xffffffffu, x, dd);
        if (lane >= dd) x += y;
    }
    if (lane == 31) wsum[wid] = x;
    __syncthreads();
    if (wid == 0) {
        int s = wsum[lane];
        #pragma unroll
        for (int dd = 1; dd < 32; dd <<= 1) {
            int y = __shfl_up_sync(0xffffffffu, s, dd);
            if (lane >= dd) s += y;
        }
        wsum[lane] = s;
    }
    __syncthreads();
    int base = (wid > 0) ? wsum[wid - 1] : 0;
    int incl = x + base;
    if (i < NSCAN) g_off[i] = incl - v;          // exclusive
    if (tid == SCAN_BLK - 1) g_part[blockIdx.x] = incl;
}

// Scan phase 2: exclusive scan of 49 block totals (one warp-pair).
__global__ void kgcn_scan2_kernel() {
    __shared__ int wtot[2];
    int tid = threadIdx.x;                       // 64 threads
    int v = (tid < SCAN_NBLK) ? g_part[tid] : 0;
    int lane = tid & 31, wid = tid >> 5;
    int x = v;
    #pragma unroll
    for (int dd = 1; dd < 32; dd <<= 1) {
        int y = __shfl_up_sync(0xffffffffu, x, dd);
        if (lane >= dd) x += y;
    }
    if (lane == 31) wtot[wid] = x;
    __syncthreads();
    int base = (wid == 1) ? wtot[0] : 0;
    if (tid < SCAN_NBLK) g_base[tid] = x + base - v;   // exclusive
}

// Scan phase 3: add block bases; init cursors.
__global__ void kgcn_scan3_kernel() {
    int i = blockIdx.x * blockDim.x + threadIdx.x;
    if (i < NSCAN) {
        int o = g_off[i] + g_base[i >> 10];
        g_off[i] = o;
        if (i < N_NODES) g_cursor[i] = o;
    }
}

// ---------------------------------------------------------------------------
// Scatter edge ids into CSR order: pos = cursor[dst]++, perm[pos]=(src,edge).
// ---------------------------------------------------------------------------
__global__ void kgcn_scatter_kernel(const int* __restrict__ src,
                                    const int* __restrict__ dst) {
    int e = blockIdx.x * blockDim.x + threadIdx.x;
    if (e >= N_EDGES) return;
    int d = dst[e];
    int pos = atomicAdd(&g_cursor[d], 1);
    g_perm[pos] = make_int2(src[e], e);
}

// ---------------------------------------------------------------------------
// Aggregate: h_sum[n] = sum_{e in CSR(n)} (exp_s[e]/denom[n]) * h_src[src[e]]
// 16 lanes per node; register accumulation; single clean write. No atomics.
// ---------------------------------------------------------------------------
__global__ void kgcn_aggregate_kernel(const float* __restrict__ h_src) {
    int tid  = blockIdx.x * blockDim.x + threadIdx.x;
    int node = tid >> 4;
    int sub  = tid & 15;
    if (node >= N_NODES) return;   // never taken: N*16 == grid exactly

    int beg = g_off[node];
    int end = g_off[node + 1];
    float inv = 1.0f / g_denom[node];   // inf if no edges -> loop empty, acc=0

    const float4* h4 = reinterpret_cast<const float4*>(h_src);
    float4 acc = make_float4(0.f, 0.f, 0.f, 0.f);

    int2 p = make_int2(0, 0);
    if (beg < end) p = g_perm[beg];
    for (int i = beg; i < end; i++) {
        int2 pc = p;
        if (i + 1 < end) p = g_perm[i + 1];      // prefetch next edge record
        float pi = g_exp_s[pc.y] * inv;
        float4 hv = h4[(size_t)pc.x * 16 + sub];
        acc.x = fmaf(pi, hv.x, acc.x);
        acc.y = fmaf(pi, hv.y, acc.y);
        acc.z = fmaf(pi, hv.z, acc.z);
        acc.w = fmaf(pi, hv.w, acc.w);
    }
    reinterpret_cast<float4*>(g_hsum)[(size_t)node * 16 + sub] = acc;
}

// ---------------------------------------------------------------------------
// Output GEMM: out = concat(h_dst, h_sum) @ W^T + b
// Block: 256 threads -> 64-node x 64-col tile; thread: 4 nodes x 4 cols.
// 782 blocks (5.3/SM) fixes R2's grid starvation. h_s stride 33 kills the
// 2-way bank conflict on the node-broadcast loads.
// ---------------------------------------------------------------------------
#define HS_STRIDE 33
__global__ void __launch_bounds__(256) kgcn_out_kernel(
        const float* __restrict__ h_dst,
        const float* __restrict__ W,
        const float* __restrict__ b,
        float* __restrict__ out) {
    __shared__ float W_s[128 * 64];          // [k][j] transposed, 32KB
    __shared__ float h_s[64 * HS_STRIDE];    // [local node][kk], padded

    const int tid = threadIdx.x;
    for (int i = tid; i < 64 * 128; i += 256) {
        int j = i >> 7;     // out col
        int k = i & 127;    // in  idx
        W_s[k * 64 + j] = W[i];
    }

    const int tx = tid & 15;      // cols 4*tx..4*tx+3
    const int ty = tid >> 4;      // nodes 4*ty..4*ty+3
    const int node0 = blockIdx.x * 64;

    float acc[4][4];
    #pragma unroll
    for (int n = 0; n < 4; n++)
        acc[n][0] = acc[n][1] = acc[n][2] = acc[n][3] = 0.f;

    #pragma unroll
    for (int c = 0; c < 4; c++) {
        const float* srcp = (c < 2) ? h_dst : g_hsum;
        const int kof4 = (c & 1) * 8;

        __syncthreads();
        #pragma unroll
        for (int r = 0; r < 2; r++) {
            int idx = tid + r * 256;    // 0..511
            int n   = idx >> 3;
            int q   = idx & 7;
            int gn  = node0 + n;
            float4 v = make_float4(0.f, 0.f, 0.f, 0.f);
            if (gn < N_NODES)
                v = reinterpret_cast<const float4*>(srcp)[(size_t)gn * 16 + kof4 + q];
            int base = n * HS_STRIDE + q * 4;
            h_s[base + 0] = v.x; h_s[base + 1] = v.y;
            h_s[base + 2] = v.z; h_s[base + 3] = v.w;
        }
        __syncthreads();

        const float* Wrow = &W_s[(c * 32) * 64 + 4 * tx];
        #pragma unroll 8
        for (int kk = 0; kk < 32; kk++) {
            float4 w = *reinterpret_cast<const float4*>(Wrow + kk * 64);
            #pragma unroll
            for (int n = 0; n < 4; n++) {
                float hv = h_s[(4 * ty + n) * HS_STRIDE + kk];
                acc[n][0] = fmaf(hv, w.x, acc[n][0]);
                acc[n][1] = fmaf(hv, w.y, acc[n][1]);
                acc[n][2] = fmaf(hv, w.z, acc[n][2]);
                acc[n][3] = fmaf(hv, w.w, acc[n][3]);
            }
        }
    }

    float4 bb = *reinterpret_cast<const float4*>(&b[4 * tx]);
    #pragma unroll
    for (int n = 0; n < 4; n++) {
        int gn = node0 + 4 * ty + n;
        if (gn < N_NODES) {
            float4 o = make_float4(acc[n][0] + bb.x, acc[n][1] + bb.y,
                                   acc[n][2] + bb.z, acc[n][3] + bb.w);
            reinterpret_cast<float4*>(out)[(size_t)gn * 16 + tx] = o;
        }
    }
}

// ---------------------------------------------------------------------------
// Launch.  Inputs: 0 h_src, 1 h_dst, 2 e, 3 src, 4 dst, 5 W, 6 b
// ---------------------------------------------------------------------------
extern "C" void kernel_launch(void* const* d_in, const int* in_sizes, int n_in,
                              void* d_out, int out_size) {
    const float* h_src = (const float*)d_in[0];
    const float* h_dst = (const float*)d_in[1];
    const float* e     = (const float*)d_in[2];
    const int*   src   = (const int*)d_in[3];
    const int*   dst   = (const int*)d_in[4];
    const float* W     = (const float*)d_in[5];
    const float* b     = (const float*)d_in[6];
    float* out = (float*)d_out;

    kgcn_zero_kernel<<<(NSCAN + 511) / 512, 512>>>();
    kgcn_score_kernel<<<50000, 256>>>(h_src, e, src, dst);       // 16 thr/edge
    kgcn_scan1_kernel<<<SCAN_NBLK, SCAN_BLK>>>();
    kgcn_scan2_kernel<<<1, 64>>>();
    kgcn_scan3_kernel<<<(NSCAN + 255) / 256, 256>>>();
    kgcn_scatter_kernel<<<(N_EDGES + 255) / 256, 256>>>(src, dst);
    kgcn_aggregate_kernel<<<(N_NODES * 16) / 256, 256>>>(h_src); // 16 thr/node
    kgcn_out_kernel<<<(N_NODES + 63) / 64, 256>>>(h_dst, W, b, out);
}

// round 4
// speedup vs baseline: 1.3771x; 1.3771x over previous
#include <cuda_runtime.h>
#include <cuda_bf16.h>

#define N_NODES 50000
#define N_EDGES 800000
#define D 64

// ---- device-global scratch (no allocations allowed) ----
__device__ __align__(16) float g_denom[N_NODES];
__device__ __align__(16) float g_hunnorm[N_NODES * D];   // un-normalized msg sums

// ---------------------------------------------------------------------------
// Zero accumulators (13MB) — must rerun every launch (graph replays).
// ---------------------------------------------------------------------------
__global__ void kgcn_zero_kernel() {
    int i = blockIdx.x * blockDim.x + threadIdx.x;
    int stride = gridDim.x * blockDim.x;
    float4 z = make_float4(0.f, 0.f, 0.f, 0.f);
    float4* h4 = reinterpret_cast<float4*>(g_hunnorm);
    const int TOT_H4 = N_NODES * D / 4;
    for (int idx = i; idx < TOT_H4; idx += stride) h4[idx] = z;
    float4* d4 = reinterpret_cast<float4*>(g_denom);
    const int TOT_D4 = N_NODES / 4;
    for (int idx = i; idx < TOT_D4; idx += stride) d4[idx] = z;
}

// ---------------------------------------------------------------------------
// Fused edge kernel: one pass over edges.
//   ex = exp(dot(h_src[src], e))
//   denom[dst]    += ex                (scalar atomic, lane 0)
//   hunnorm[dst]  += ex * h_src[src]   (red.v4 per lane)
// Half-warp (16 lanes x float4) per edge; xor-reduce leaves the full dot in
// every lane, so each lane computes expf locally (no broadcast shfl).
// Normalization is deferred to the GEMM (h_sum = hunnorm/denom).
// ---------------------------------------------------------------------------
__global__ void kgcn_edge_kernel(const float* __restrict__ h_src,
                                 const float* __restrict__ e,
                                 const int* __restrict__ src,
                                 const int* __restrict__ dst) {
    int tid  = blockIdx.x * blockDim.x + threadIdx.x;
    int edge = tid >> 4;
    int sub  = tid & 15;
    if (edge >= N_EDGES) return;   // never taken: E*16 == grid exactly

    int s = src[edge];
    int d = dst[edge];
    float4 hv = reinterpret_cast<const float4*>(h_src)[(size_t)s * 16 + sub];
    float4 ev = reinterpret_cast<const float4*>(e)[(size_t)edge * 16 + sub];

    float dot = hv.x * ev.x + hv.y * ev.y + hv.z * ev.z + hv.w * ev.w;
    dot += __shfl_xor_sync(0xffffffffu, dot, 1);
    dot += __shfl_xor_sync(0xffffffffu, dot, 2);
    dot += __shfl_xor_sync(0xffffffffu, dot, 4);
    dot += __shfl_xor_sync(0xffffffffu, dot, 8);
    // all 16 lanes of the half-warp now hold the full dot product

    float ex = __expf(dot);

    float* addr = &g_hunnorm[(size_t)d * D + sub * 4];
    asm volatile("red.global.add.v4.f32 [%0], {%1, %2, %3, %4};"
                 :: "l"(addr),
                    "f"(ex * hv.x), "f"(ex * hv.y), "f"(ex * hv.z), "f"(ex * hv.w)
                 : "memory");
    if (sub == 0) atomicAdd(&g_denom[d], ex);
}

// ---------------------------------------------------------------------------
// Output GEMM: out = concat(h_dst, hunnorm/denom) @ W^T + b
// Block: 256 threads -> 64-node x 64-col tile; thread: 4 nodes x 4 cols.
// Normalization folded into the staging of chunks 2-3.
// ---------------------------------------------------------------------------
#define HS_STRIDE 33
__global__ void __launch_bounds__(256) kgcn_out_kernel(
        const float* __restrict__ h_dst,
        const float* __restrict__ W,
        const float* __restrict__ b,
        float* __restrict__ out) {
    __shared__ float W_s[128 * 64];          // [k][j] transposed, 32KB
    __shared__ float h_s[64 * HS_STRIDE];    // [local node][kk], padded

    const int tid = threadIdx.x;
    for (int i = tid; i < 64 * 128; i += 256) {
        int j = i >> 7;     // out col
        int k = i & 127;    // in  idx
        W_s[k * 64 + j] = W[i];
    }

    const int tx = tid & 15;      // cols 4*tx..4*tx+3
    const int ty = tid >> 4;      // nodes 4*ty..4*ty+3
    const int node0 = blockIdx.x * 64;

    float acc[4][4];
    #pragma unroll
    for (int n = 0; n < 4; n++)
        acc[n][0] = acc[n][1] = acc[n][2] = acc[n][3] = 0.f;

    #pragma unroll
    for (int c = 0; c < 4; c++) {
        const float* srcp = (c < 2) ? h_dst : g_hunnorm;
        const int kof4 = (c & 1) * 8;

        __syncthreads();
        #pragma unroll
        for (int r = 0; r < 2; r++) {
            int idx = tid + r * 256;    // 0..511
            int n   = idx >> 3;
            int q   = idx & 7;
            int gn  = node0 + n;
            float4 v = make_float4(0.f, 0.f, 0.f, 0.f);
            if (gn < N_NODES) {
                v = reinterpret_cast<const float4*>(srcp)[(size_t)gn * 16 + kof4 + q];
                if (c >= 2) {
                    float dn = g_denom[gn];
                    float inv = (dn != 0.f) ? (1.0f / dn) : 0.f;  // edge-less node -> 0
                    v.x *= inv; v.y *= inv; v.z *= inv; v.w *= inv;
                }
            }
            int base = n * HS_STRIDE + q * 4;
            h_s[base + 0] = v.x; h_s[base + 1] = v.y;
            h_s[base + 2] = v.z; h_s[base + 3] = v.w;
        }
        __syncthreads();

        const float* Wrow = &W_s[(c * 32) * 64 + 4 * tx];
        #pragma unroll 8
        for (int kk = 0; kk < 32; kk++) {
            float4 w = *reinterpret_cast<const float4*>(Wrow + kk * 64);
            #pragma unroll
            for (int n = 0; n < 4; n++) {
                float hv = h_s[(4 * ty + n) * HS_STRIDE + kk];
                acc[n][0] = fmaf(hv, w.x, acc[n][0]);
                acc[n][1] = fmaf(hv, w.y, acc[n][1]);
                acc[n][2] = fmaf(hv, w.z, acc[n][2]);
                acc[n][3] = fmaf(hv, w.w, acc[n][3]);
            }
        }
    }

    float4 bb = *reinterpret_cast<const float4*>(&b[4 * tx]);
    #pragma unroll
    for (int n = 0; n < 4; n++) {
        int gn = node0 + 4 * ty + n;
        if (gn < N_NODES) {
            float4 o = make_float4(acc[n][0] + bb.x, acc[n][1] + bb.y,
                                   acc[n][2] + bb.z, acc[n][3] + bb.w);
            reinterpret_cast<float4*>(out)[(size_t)gn * 16 + tx] = o;
        }
    }
}

// ---------------------------------------------------------------------------
// Launch.  Inputs: 0 h_src, 1 h_dst, 2 e, 3 src, 4 dst, 5 W, 6 b
// ---------------------------------------------------------------------------
extern "C" void kernel_launch(void* const* d_in, const int* in_sizes, int n_in,
                              void* d_out, int out_size) {
    const float* h_src = (const float*)d_in[0];
    const float* h_dst = (const float*)d_in[1];
    const float* e     = (const float*)d_in[2];
    const int*   src   = (const int*)d_in[3];
    const int*   dst   = (const int*)d_in[4];
    const float* W     = (const float*)d_in[5];
    const float* b     = (const float*)d_in[6];
    float* out = (float*)d_out;

    kgcn_zero_kernel<<<592, 256>>>();
    // 800000 edges * 16 threads/edge = 50000 blocks * 256
    kgcn_edge_kernel<<<50000, 256>>>(h_src, e, src, dst);
    kgcn_out_kernel<<<(N_NODES + 63) / 64, 256>>>(h_dst, W, b, out);
}